// round 1
// baseline (speedup 1.0000x reference)
#include <cuda_runtime.h>
#include <cmath>

// Problem constants
#define BB   4
#define SS   1024
#define DD   1024
#define HH   16
#define DKH  64
#define LL   4
#define FF   4096
#define VV   32000
#define NT   (BB*SS)   // 4096 tokens

// Scratch (device globals — no runtime allocation allowed)
__device__ float g_h  [NT*(size_t)DD];
__device__ float g_q  [NT*(size_t)DD];
__device__ float g_k  [NT*(size_t)DD];
__device__ float g_v  [NT*(size_t)DD];
__device__ float g_ctx[NT*(size_t)DD];
__device__ float g_tmp[NT*(size_t)DD];
__device__ float g_ff [NT*(size_t)FF];

// ---------------------------------------------------------------------------
// Embedding + sinusoidal positional encoding
// ---------------------------------------------------------------------------
__global__ __launch_bounds__(256) void embed_kernel(const int* __restrict__ x,
                                                    const float* __restrict__ emb,
                                                    float* __restrict__ h)
{
    int t = blockIdx.x;          // token 0..NT-1
    int s = t & (SS - 1);        // position in sequence
    int tok = x[t];
    const float* e = emb + (size_t)tok * DD;
    float* out = h + (size_t)t * DD;
    const float negln = -9.210340371976184f; // -ln(10000)
    for (int d = threadIdx.x; d < DD; d += blockDim.x) {
        int i2 = (d >> 1) * 2;                       // even index used in arange(0, D, 2)
        float div = expf((float)i2 * (negln / (float)DD));
        float ang = (float)s * div;
        float pe = (d & 1) ? cosf(ang) : sinf(ang);
        out[d] = e[d] * 32.0f + pe;                  // sqrt(1024) = 32
    }
}

// ---------------------------------------------------------------------------
// GEMM: C[M,N] = A[M,K] @ B[K,N] (+bias) (+GELU)
// 128x128 block tile, BK=16, 256 threads, 8x8 per thread.
// Inner product uses packed fma.rn.f32x2 (2 fp32 FMA per instruction) with the
// pair laid along N so B pairs are read directly as 64-bit LDS (no pack insns).
// Requires M%128==0, N%128==0, K%16==0 (true for all calls here).
// ---------------------------------------------------------------------------
template<int ACT>  // 0 = none, 1 = exact GELU
__global__ __launch_bounds__(256) void gemm_kernel(const float* __restrict__ A,
                                                   const float* __restrict__ B,
                                                   const float* __restrict__ bias,
                                                   float* __restrict__ C,
                                                   int M, int N, int K)
{
    __shared__ float As[16][128];   // [k][m]
    __shared__ float Bs[16][128];   // [k][n]

    const int tid = threadIdx.x;
    const int tx = tid & 15;        // 16 col groups of 8
    const int ty = tid >> 4;        // 16 row groups of 8
    const int rowBase = blockIdx.y * 128;
    const int colBase = blockIdx.x * 128;

    unsigned long long acc[8][4];   // 8 rows x 4 packed-f32x2 col pairs
    #pragma unroll
    for (int i = 0; i < 8; i++)
        #pragma unroll
        for (int j = 0; j < 4; j++) acc[i][j] = 0ull;

    for (int k0 = 0; k0 < K; k0 += 16) {
        // A tile: 128 rows x 16 k (float4 along K, transpose into As[k][m])
        #pragma unroll
        for (int r = 0; r < 2; r++) {
            int idx = tid + r * 256;         // 0..511
            int m   = idx >> 2;
            int kq  = (idx & 3) * 4;
            float4 a4 = *reinterpret_cast<const float4*>(
                &A[(size_t)(rowBase + m) * K + k0 + kq]);
            As[kq + 0][m] = a4.x;
            As[kq + 1][m] = a4.y;
            As[kq + 2][m] = a4.z;
            As[kq + 3][m] = a4.w;
        }
        // B tile: 16 k x 128 n (float4 along N)
        #pragma unroll
        for (int r = 0; r < 2; r++) {
            int idx = tid + r * 256;
            int kk  = idx >> 5;
            int nq  = (idx & 31) * 4;
            *reinterpret_cast<float4*>(&Bs[kk][nq]) =
                *reinterpret_cast<const float4*>(
                    &B[(size_t)(k0 + kk) * N + colBase + nq]);
        }
        __syncthreads();

        #pragma unroll
        for (int kk = 0; kk < 16; kk++) {
            unsigned long long bp[4];
            const unsigned long long* br =
                reinterpret_cast<const unsigned long long*>(&Bs[kk][0]);
            #pragma unroll
            for (int j = 0; j < 4; j++) bp[j] = br[tx * 4 + j];
            #pragma unroll
            for (int i = 0; i < 8; i++) {
                float a = As[kk][ty * 8 + i];
                unsigned long long ap;
                asm("mov.b64 %0, {%1, %1};" : "=l"(ap) : "f"(a));
                #pragma unroll
                for (int j = 0; j < 4; j++) {
                    asm("fma.rn.f32x2 %0, %1, %2, %0;"
                        : "+l"(acc[i][j]) : "l"(ap), "l"(bp[j]));
                }
            }
        }
        __syncthreads();
    }

    // Epilogue
    #pragma unroll
    for (int i = 0; i < 8; i++) {
        int row = rowBase + ty * 8 + i;
        float out[8];
        #pragma unroll
        for (int j = 0; j < 4; j++) {
            float lo, hi;
            asm("mov.b64 {%0, %1}, %2;" : "=f"(lo), "=f"(hi) : "l"(acc[i][j]));
            out[2 * j]     = lo;
            out[2 * j + 1] = hi;
        }
        #pragma unroll
        for (int jj = 0; jj < 8; jj++) {
            int col = colBase + tx * 8 + jj;
            float v = out[jj];
            if (bias) v += bias[col];
            if (ACT == 1) v = 0.5f * v * (1.0f + erff(v * 0.7071067811865476f));
            out[jj] = v;
        }
        float4* cp = reinterpret_cast<float4*>(&C[(size_t)row * N + colBase + tx * 8]);
        cp[0] = make_float4(out[0], out[1], out[2], out[3]);
        cp[1] = make_float4(out[4], out[5], out[6], out[7]);
    }
}

// ---------------------------------------------------------------------------
// Flash attention (fp32). One thread owns one q row. 32-row K/V tiles in SMEM.
// Grid: (B*H, S/64), Block: 64 threads.
// ---------------------------------------------------------------------------
__global__ __launch_bounds__(64) void attn_kernel(const float* __restrict__ Q,
                                                  const float* __restrict__ K,
                                                  const float* __restrict__ V,
                                                  const int* __restrict__ x,
                                                  float* __restrict__ O)
{
    __shared__ float Ks[32][64];
    __shared__ float Vs[32][64];
    __shared__ int   validS[32];

    const int bh = blockIdx.x;
    const int b  = bh >> 4;
    const int h  = bh & 15;
    const int qt = blockIdx.y;
    const int tid = threadIdx.x;       // 0..63
    const int qrow = qt * 64 + tid;
    const int tQ = b * SS + qrow;

    const float* qp = Q + (size_t)tQ * DD + h * DKH;
    float qreg[64], acc[64];
    #pragma unroll
    for (int d = 0; d < 64; d += 4) {
        float4 f = *reinterpret_cast<const float4*>(qp + d);
        qreg[d] = f.x; qreg[d+1] = f.y; qreg[d+2] = f.z; qreg[d+3] = f.w;
    }
    #pragma unroll
    for (int d = 0; d < 64; d++) acc[d] = 0.0f;

    float mrun = -1e30f, lsum = 0.0f;
    const int ntiles = 2 * qt + 2;     // 32-row tiles needed to cover causal span

    for (int kt = 0; kt < ntiles; kt++) {
        const int kbase = kt * 32;
        // Cooperative load of K/V tiles (each thread one column, 32 rows)
        #pragma unroll 4
        for (int i = 0; i < 32; i++) {
            size_t off = (size_t)(b * SS + kbase + i) * DD + h * DKH + tid;
            Ks[i][tid] = K[off];
            Vs[i][tid] = V[off];
        }
        if (tid < 32) validS[tid] = (x[b * SS + kbase + tid] != 0);
        __syncthreads();

        int jmax = qrow - kbase + 1;
        if (jmax > 32) jmax = 32;
        if (jmax > 0) {
            float s[32];
            float tmax = -1e30f;
            #pragma unroll
            for (int j = 0; j < 32; j++) {
                if (j < jmax) {
                    float sum = 0.0f;
                    const float4* kr = reinterpret_cast<const float4*>(Ks[j]);
                    #pragma unroll
                    for (int dq = 0; dq < 16; dq++) {
                        float4 k4 = kr[dq];
                        sum += qreg[4*dq]   * k4.x;
                        sum += qreg[4*dq+1] * k4.y;
                        sum += qreg[4*dq+2] * k4.z;
                        sum += qreg[4*dq+3] * k4.w;
                    }
                    sum *= 0.125f;                       // 1/sqrt(64)
                    if (!validS[j]) sum = -1e30f;
                    s[j] = sum;
                    tmax = fmaxf(tmax, sum);
                } else {
                    s[j] = -1e30f;
                }
            }
            float mnew = fmaxf(mrun, tmax);
            float corr = __expf(mrun - mnew);
            lsum *= corr;
            #pragma unroll
            for (int d = 0; d < 64; d++) acc[d] *= corr;
            mrun = mnew;
            #pragma unroll
            for (int j = 0; j < 32; j++) {
                float p = __expf(s[j] - mrun);           // 0 for masked lanes
                lsum += p;
                const float4* vr = reinterpret_cast<const float4*>(Vs[j]);
                #pragma unroll
                for (int dq = 0; dq < 16; dq++) {
                    float4 v4 = vr[dq];
                    acc[4*dq]   += p * v4.x;
                    acc[4*dq+1] += p * v4.y;
                    acc[4*dq+2] += p * v4.z;
                    acc[4*dq+3] += p * v4.w;
                }
            }
        }
        __syncthreads();
    }

    float inv = 1.0f / lsum;
    float* op = O + (size_t)tQ * DD + h * DKH;
    #pragma unroll
    for (int d = 0; d < 64; d += 4) {
        float4 o4 = make_float4(acc[d]*inv, acc[d+1]*inv, acc[d+2]*inv, acc[d+3]*inv);
        *reinterpret_cast<float4*>(op + d) = o4;
    }
}

// ---------------------------------------------------------------------------
// Residual add + LayerNorm (in place on h). One block per token, 256 threads.
// ---------------------------------------------------------------------------
__device__ __forceinline__ float block_sum(float v, float* red)
{
    #pragma unroll
    for (int o = 16; o > 0; o >>= 1) v += __shfl_xor_sync(0xffffffffu, v, o);
    int w = threadIdx.x >> 5;
    if ((threadIdx.x & 31) == 0) red[w] = v;
    __syncthreads();
    if (threadIdx.x < 32) {
        float t = (threadIdx.x < 8) ? red[threadIdx.x] : 0.0f;
        #pragma unroll
        for (int o = 4; o > 0; o >>= 1) t += __shfl_xor_sync(0xffffffffu, t, o);
        if (threadIdx.x == 0) red[0] = t;
    }
    __syncthreads();
    float r = red[0];
    __syncthreads();
    return r;
}

__global__ __launch_bounds__(256) void add_ln_kernel(float* __restrict__ h,
                                                     const float* __restrict__ r,
                                                     const float* __restrict__ g,
                                                     const float* __restrict__ bta)
{
    __shared__ float red[32];
    const int t = blockIdx.x;
    const int tid = threadIdx.x;
    float v[4];
    float sum = 0.0f;
    #pragma unroll
    for (int i = 0; i < 4; i++) {
        int d = tid + i * 256;
        float val = h[(size_t)t * DD + d] + r[(size_t)t * DD + d];
        v[i] = val;
        sum += val;
    }
    float tot = block_sum(sum, red);
    float mu = tot * (1.0f / (float)DD);
    float sq = 0.0f;
    #pragma unroll
    for (int i = 0; i < 4; i++) { float dvi = v[i] - mu; sq += dvi * dvi; }
    float var = block_sum(sq, red) * (1.0f / (float)DD);
    float rs = rsqrtf(var + 1e-5f);
    #pragma unroll
    for (int i = 0; i < 4; i++) {
        int d = tid + i * 256;
        h[(size_t)t * DD + d] = (v[i] - mu) * rs * g[d] + bta[d];
    }
}

// ---------------------------------------------------------------------------
// Launch
// ---------------------------------------------------------------------------
extern "C" void kernel_launch(void* const* d_in, const int* in_sizes, int n_in,
                              void* d_out, int out_size)
{
    const int*   x    = (const int*)  d_in[0];
    const float* emb  = (const float*)d_in[1];
    const float* Wq   = (const float*)d_in[2];
    const float* Wk   = (const float*)d_in[3];
    const float* Wv   = (const float*)d_in[4];
    const float* Wo   = (const float*)d_in[5];
    const float* bo   = (const float*)d_in[6];
    const float* ln1g = (const float*)d_in[7];
    const float* ln1b = (const float*)d_in[8];
    const float* ln2g = (const float*)d_in[9];
    const float* ln2b = (const float*)d_in[10];
    const float* W1   = (const float*)d_in[11];
    const float* b1   = (const float*)d_in[12];
    const float* W2   = (const float*)d_in[13];
    const float* b2   = (const float*)d_in[14];
    const float* Wout = (const float*)d_in[15];
    const float* bout = (const float*)d_in[16];
    float* out = (float*)d_out;

    void* p;
    cudaGetSymbolAddress(&p, g_h);   float* h   = (float*)p;
    cudaGetSymbolAddress(&p, g_q);   float* q   = (float*)p;
    cudaGetSymbolAddress(&p, g_k);   float* k   = (float*)p;
    cudaGetSymbolAddress(&p, g_v);   float* v   = (float*)p;
    cudaGetSymbolAddress(&p, g_ctx); float* ctx = (float*)p;
    cudaGetSymbolAddress(&p, g_tmp); float* tmp = (float*)p;
    cudaGetSymbolAddress(&p, g_ff);  float* ff  = (float*)p;

    embed_kernel<<<NT, 256>>>(x, emb, h);

    const dim3 blk(256);
    const dim3 gD(DD / 128, NT / 128);   // N=1024
    const dim3 gF(FF / 128, NT / 128);   // N=4096
    const dim3 gV(VV / 128, NT / 128);   // N=32000

    for (int l = 0; l < LL; l++) {
        const float* wq = Wq + (size_t)l * DD * DD;
        const float* wk = Wk + (size_t)l * DD * DD;
        const float* wv = Wv + (size_t)l * DD * DD;
        const float* wo = Wo + (size_t)l * DD * DD;
        const float* w1 = W1 + (size_t)l * DD * FF;
        const float* w2 = W2 + (size_t)l * FF * DD;

        gemm_kernel<0><<<gD, blk>>>(h, wq, nullptr, q, NT, DD, DD);
        gemm_kernel<0><<<gD, blk>>>(h, wk, nullptr, k, NT, DD, DD);
        gemm_kernel<0><<<gD, blk>>>(h, wv, nullptr, v, NT, DD, DD);

        attn_kernel<<<dim3(BB * HH, SS / 64), 64>>>(q, k, v, x, ctx);

        gemm_kernel<0><<<gD, blk>>>(ctx, wo, bo + l * DD, tmp, NT, DD, DD);
        add_ln_kernel<<<NT, 256>>>(h, tmp, ln1g + l * DD, ln1b + l * DD);

        gemm_kernel<1><<<gF, blk>>>(h, w1, b1 + l * FF, ff, NT, FF, DD);
        gemm_kernel<0><<<gD, blk>>>(ff, w2, b2 + l * DD, tmp, NT, DD, FF);
        add_ln_kernel<<<NT, 256>>>(h, tmp, ln2g + l * DD, ln2b + l * DD);
    }

    gemm_kernel<0><<<gV, blk>>>(h, Wout, bout, out, NT, VV, DD);
}

// round 3
// speedup vs baseline: 2.0767x; 2.0767x over previous
#include <cuda_runtime.h>
#include <cuda_bf16.h>
#include <cstdint>
#include <cmath>

// Problem constants
#define BB   4
#define SS   1024
#define DD   1024
#define HH   16
#define DKH  64
#define LL   4
#define FF   4096
#define VV   32000
#define NT   (BB*SS)   // 4096 tokens
#define QKVW 3072      // packed q|k|v width

// GEMM tile config (mma.sync path)
#define BM 128
#define BN 128
#define BK 64                      // bf16 elems per stage
#define ROWB 144                   // 128B data + 16B pad per SMEM row
#define MATB (128*ROWB)            // one 128xBK bf16 matrix: 18432 B
#define STAGEB (4*MATB)            // Ahi|Alo|Bhi|Blo : 73728 B
#define GEMM_SMEM (2*STAGEB)       // 147456 B

// ---------------------------------------------------------------------------
// Scratch (device globals — no runtime allocation allowed)
// ---------------------------------------------------------------------------
__device__ float g_h  [NT*(size_t)DD];
__device__ float g_qkv[NT*(size_t)QKVW];
__device__ float g_ctx[NT*(size_t)DD];
__device__ float g_tmp[NT*(size_t)DD];
__device__ float g_ff [NT*(size_t)FF];
__device__ __nv_bfloat16 g_ahi[NT*(size_t)FF];
__device__ __nv_bfloat16 g_alo[NT*(size_t)FF];
__device__ __nv_bfloat16 g_whi[(size_t)VV*DD];
__device__ __nv_bfloat16 g_wlo[(size_t)VV*DD];

// ---------------------------------------------------------------------------
// PTX helpers (arch-agnostic: sm_80-era instructions only)
// ---------------------------------------------------------------------------
__device__ __forceinline__ uint32_t smem_u32(const void* p) {
    uint32_t a;
    asm("{ .reg .u64 t; cvta.to.shared.u64 t, %1; cvt.u32.u64 %0, t; }" : "=r"(a) : "l"(p));
    return a;
}
__device__ __forceinline__ void cp_async16(uint32_t dst, const void* src) {
    asm volatile("cp.async.cg.shared.global [%0], [%1], 16;" :: "r"(dst), "l"(src));
}
__device__ __forceinline__ void cp_commit() {
    asm volatile("cp.async.commit_group;");
}
__device__ __forceinline__ void cp_wait1() {
    asm volatile("cp.async.wait_group 1;");
}
__device__ __forceinline__ void cp_wait0() {
    asm volatile("cp.async.wait_group 0;");
}
__device__ __forceinline__ void ldmx4(uint32_t addr, uint32_t& r0, uint32_t& r1,
                                      uint32_t& r2, uint32_t& r3) {
    asm volatile("ldmatrix.sync.aligned.m8n8.x4.shared.b16 {%0,%1,%2,%3}, [%4];"
                 : "=r"(r0), "=r"(r1), "=r"(r2), "=r"(r3) : "r"(addr));
}
__device__ __forceinline__ void mma_bf16(float* c, const uint32_t* a, const uint32_t* b) {
    asm volatile("mma.sync.aligned.m16n8k16.row.col.f32.bf16.bf16.f32 "
                 "{%0,%1,%2,%3}, {%4,%5,%6,%7}, {%8,%9}, {%0,%1,%2,%3};"
                 : "+f"(c[0]), "+f"(c[1]), "+f"(c[2]), "+f"(c[3])
                 : "r"(a[0]), "r"(a[1]), "r"(a[2]), "r"(a[3]), "r"(b[0]), "r"(b[1]));
}

// ---------------------------------------------------------------------------
// Embedding + sinusoidal positional encoding
// ---------------------------------------------------------------------------
__global__ __launch_bounds__(256) void embed_kernel(const int* __restrict__ x,
                                                    const float* __restrict__ emb,
                                                    float* __restrict__ h)
{
    int t = blockIdx.x;
    int s = t & (SS - 1);
    int tok = x[t];
    const float* e = emb + (size_t)tok * DD;
    float* out = h + (size_t)t * DD;
    const float negln = -9.210340371976184f;
    for (int d = threadIdx.x; d < DD; d += blockDim.x) {
        int i2 = (d >> 1) * 2;
        float div = expf((float)i2 * (negln / (float)DD));
        float ang = (float)s * div;
        float pe = (d & 1) ? cosf(ang) : sinf(ang);
        out[d] = e[d] * 32.0f + pe;
    }
}

// ---------------------------------------------------------------------------
// fp32 -> bf16 hi/lo split (elementwise)
// ---------------------------------------------------------------------------
__global__ __launch_bounds__(256) void cvt_act_kernel(const float* __restrict__ X,
                                                      __nv_bfloat16* __restrict__ hi,
                                                      __nv_bfloat16* __restrict__ lo,
                                                      int n)
{
    for (int i = blockIdx.x * blockDim.x + threadIdx.x; i < n; i += gridDim.x * blockDim.x) {
        float x = X[i];
        __nv_bfloat16 h = __float2bfloat16(x);
        hi[i] = h;
        lo[i] = __float2bfloat16(x - __bfloat162float(h));
    }
}

// ---------------------------------------------------------------------------
// Weight transpose + split: W[K,N] fp32 -> T_hi/T_lo[N,K] bf16
// Grid (N/32, K/32), block (32,8)
// ---------------------------------------------------------------------------
__global__ __launch_bounds__(256) void transp_cvt_kernel(const float* __restrict__ W,
                                                         __nv_bfloat16* __restrict__ Thi,
                                                         __nv_bfloat16* __restrict__ Tlo,
                                                         int K, int N)
{
    __shared__ float t[32][33];
    int n0 = blockIdx.x * 32, k0 = blockIdx.y * 32;
    int tx = threadIdx.x, ty = threadIdx.y;
    #pragma unroll
    for (int i = 0; i < 4; i++)
        t[ty + i * 8][tx] = W[(size_t)(k0 + ty + i * 8) * N + n0 + tx];
    __syncthreads();
    #pragma unroll
    for (int i = 0; i < 4; i++) {
        int row = ty + i * 8;
        float x = t[tx][row];
        __nv_bfloat16 h = __float2bfloat16(x);
        float l = x - __bfloat162float(h);
        size_t o = (size_t)(n0 + row) * K + k0 + tx;
        Thi[o] = h;
        Tlo[o] = __float2bfloat16(l);
    }
}

// ---------------------------------------------------------------------------
// bf16x3 GEMM via mma.sync: C[M,N] = A[M,K] @ Bt[N,K]^T (+bias)(+GELU)
// A hi/lo bf16 [M,K]; B hi/lo bf16 [N,K] (pre-transposed).
// BM=BN=128, BK=64, 256 threads (8 warps, 64x32 warp tiles),
// cp.async double buffer, fp32 accumulators in registers.
// ---------------------------------------------------------------------------
__device__ __forceinline__ void stage_load(uint32_t sdst,
                                           const __nv_bfloat16* Ahi, const __nv_bfloat16* Alo,
                                           const __nv_bfloat16* Bhi, const __nv_bfloat16* Blo,
                                           int rowBase, int colBase, int K, int k0, int tid)
{
    #pragma unroll
    for (int i = 0; i < 4; i++) {
        int idx = tid + i * 256;           // 0..1023
        int r  = idx >> 3;
        int ch = idx & 7;
        uint32_t so = (uint32_t)r * ROWB + (uint32_t)ch * 16;
        size_t gA = (size_t)(rowBase + r) * K + k0 + ch * 8;
        size_t gB = (size_t)(colBase + r) * K + k0 + ch * 8;
        cp_async16(sdst + so,            Ahi + gA);
        cp_async16(sdst + MATB + so,     Alo + gA);
        cp_async16(sdst + 2 * MATB + so, Bhi + gB);
        cp_async16(sdst + 3 * MATB + so, Blo + gB);
    }
}

template<int ACT>
__global__ __launch_bounds__(256) void gemm_mma(const __nv_bfloat16* __restrict__ Ahi,
                                                const __nv_bfloat16* __restrict__ Alo,
                                                const __nv_bfloat16* __restrict__ Bhi,
                                                const __nv_bfloat16* __restrict__ Blo,
                                                const float* __restrict__ bias,
                                                float* __restrict__ C,
                                                int M, int N, int K)
{
    extern __shared__ char smem[];
    const uint32_t sb = smem_u32(smem);
    const int tid  = threadIdx.x;
    const int wid  = tid >> 5;
    const int lane = tid & 31;
    const int rowBase = blockIdx.y * BM;
    const int colBase = blockIdx.x * BN;
    const int m0 = (wid >> 2) * 64;     // warp M offset in CTA tile
    const int n0 = (wid & 3) * 32;      // warp N offset

    const int g  = lane >> 3;
    const int lr = lane & 7;

    float acc[4][4][4];
    #pragma unroll
    for (int mt = 0; mt < 4; mt++)
        #pragma unroll
        for (int nt = 0; nt < 4; nt++)
            #pragma unroll
            for (int e = 0; e < 4; e++) acc[mt][nt][e] = 0.0f;

    const int KT = K / BK;

    stage_load(sb, Ahi, Alo, Bhi, Blo, rowBase, colBase, K, 0, tid);
    cp_commit();

    for (int it = 0; it < KT; it++) {
        const int buf = it & 1;
        if (it + 1 < KT) {
            stage_load(sb + (buf ^ 1) * STAGEB, Ahi, Alo, Bhi, Blo,
                       rowBase, colBase, K, (it + 1) * BK, tid);
            cp_commit();
            cp_wait1();
        } else {
            cp_wait0();
        }
        __syncthreads();

        const uint32_t aB = sb + buf * STAGEB;
        const uint32_t bB = aB + 2 * MATB;

        #pragma unroll
        for (int ks = 0; ks < 4; ks++) {
            // A fragments (hi & lo), 4 m16 tiles
            uint32_t Ah[4][4], Al[4][4];
            #pragma unroll
            for (int mt = 0; mt < 4; mt++) {
                int r  = m0 + mt * 16 + (g & 1) * 8 + lr;
                int ch = ks * 2 + (g >> 1);
                uint32_t ad = aB + (uint32_t)r * ROWB + (uint32_t)ch * 16;
                ldmx4(ad,        Ah[mt][0], Ah[mt][1], Ah[mt][2], Ah[mt][3]);
                ldmx4(ad + MATB, Al[mt][0], Al[mt][1], Al[mt][2], Al[mt][3]);
            }
            // B fragments (hi & lo), 4 n8 tiles (2x ldmatrix.x4)
            uint32_t Bh[4][2], Bl[4][2];
            #pragma unroll
            for (int p = 0; p < 2; p++) {
                int r  = n0 + p * 16 + (g >> 1) * 8 + lr;
                int ch = ks * 2 + (g & 1);
                uint32_t bd = bB + (uint32_t)r * ROWB + (uint32_t)ch * 16;
                ldmx4(bd,        Bh[2*p][0], Bh[2*p][1], Bh[2*p+1][0], Bh[2*p+1][1]);
                ldmx4(bd + MATB, Bl[2*p][0], Bl[2*p][1], Bl[2*p+1][0], Bl[2*p+1][1]);
            }
            // MMAs: hi*hi + hi*lo + lo*hi
            #pragma unroll
            for (int mt = 0; mt < 4; mt++)
                #pragma unroll
                for (int nt = 0; nt < 4; nt++) {
                    mma_bf16(acc[mt][nt], Ah[mt], Bh[nt]);
                    mma_bf16(acc[mt][nt], Ah[mt], Bl[nt]);
                    mma_bf16(acc[mt][nt], Al[mt], Bh[nt]);
                }
        }
        __syncthreads();
    }

    // Epilogue: c-fragment rows i/4, i/4+8 ; cols 2*(i%4)+{0,1}
    const int crow = lane >> 2;
    const int ccol = (lane & 3) * 2;
    #pragma unroll
    for (int mt = 0; mt < 4; mt++) {
        #pragma unroll
        for (int nt = 0; nt < 4; nt++) {
            int col = colBase + n0 + nt * 8 + ccol;
            float b0 = 0.0f, b1 = 0.0f;
            if (bias) { b0 = __ldg(bias + col); b1 = __ldg(bias + col + 1); }
            #pragma unroll
            for (int half = 0; half < 2; half++) {
                int row = rowBase + m0 + mt * 16 + crow + half * 8;
                float v0 = acc[mt][nt][half * 2 + 0] + b0;
                float v1 = acc[mt][nt][half * 2 + 1] + b1;
                if (ACT == 1) {
                    v0 = 0.5f * v0 * (1.0f + erff(v0 * 0.7071067811865476f));
                    v1 = 0.5f * v1 * (1.0f + erff(v1 * 0.7071067811865476f));
                }
                *reinterpret_cast<float2*>(&C[(size_t)row * N + col]) = make_float2(v0, v1);
            }
        }
    }
}

// ---------------------------------------------------------------------------
// Flash attention (fp32) on packed qkv [NT, 3072].
// ---------------------------------------------------------------------------
__global__ __launch_bounds__(64) void attn_kernel(const float* __restrict__ QKV,
                                                  const int* __restrict__ x,
                                                  float* __restrict__ O)
{
    __shared__ float Ks[32][64];
    __shared__ float Vs[32][64];
    __shared__ int   validS[32];

    const int bh = blockIdx.x;
    const int b  = bh >> 4;
    const int h  = bh & 15;
    const int qt = blockIdx.y;
    const int tid = threadIdx.x;
    const int qrow = qt * 64 + tid;
    const int tQ = b * SS + qrow;

    const float* qp = QKV + (size_t)tQ * QKVW + h * DKH;
    float qreg[64], acc[64];
    #pragma unroll
    for (int d = 0; d < 64; d += 4) {
        float4 f = *reinterpret_cast<const float4*>(qp + d);
        qreg[d] = f.x; qreg[d+1] = f.y; qreg[d+2] = f.z; qreg[d+3] = f.w;
    }
    #pragma unroll
    for (int d = 0; d < 64; d++) acc[d] = 0.0f;

    float mrun = -1e30f, lsum = 0.0f;
    const int ntiles = 2 * qt + 2;

    for (int kt = 0; kt < ntiles; kt++) {
        const int kbase = kt * 32;
        #pragma unroll 4
        for (int i = 0; i < 32; i++) {
            size_t off = (size_t)(b * SS + kbase + i) * QKVW + h * DKH + tid;
            Ks[i][tid] = QKV[off + 1024];
            Vs[i][tid] = QKV[off + 2048];
        }
        if (tid < 32) validS[tid] = (x[b * SS + kbase + tid] != 0);
        __syncthreads();

        int jmax = qrow - kbase + 1;
        if (jmax > 32) jmax = 32;
        if (jmax > 0) {
            float s[32];
            float tmax = -1e30f;
            #pragma unroll
            for (int j = 0; j < 32; j++) {
                if (j < jmax) {
                    float sum = 0.0f;
                    const float4* kr = reinterpret_cast<const float4*>(Ks[j]);
                    #pragma unroll
                    for (int dq = 0; dq < 16; dq++) {
                        float4 k4 = kr[dq];
                        sum += qreg[4*dq]   * k4.x;
                        sum += qreg[4*dq+1] * k4.y;
                        sum += qreg[4*dq+2] * k4.z;
                        sum += qreg[4*dq+3] * k4.w;
                    }
                    sum *= 0.125f;
                    if (!validS[j]) sum = -1e30f;
                    s[j] = sum;
                    tmax = fmaxf(tmax, sum);
                } else {
                    s[j] = -1e30f;
                }
            }
            float mnew = fmaxf(mrun, tmax);
            float corr = __expf(mrun - mnew);
            lsum *= corr;
            #pragma unroll
            for (int d = 0; d < 64; d++) acc[d] *= corr;
            mrun = mnew;
            #pragma unroll
            for (int j = 0; j < 32; j++) {
                float p = __expf(s[j] - mrun);
                lsum += p;
                const float4* vr = reinterpret_cast<const float4*>(Vs[j]);
                #pragma unroll
                for (int dq = 0; dq < 16; dq++) {
                    float4 v4 = vr[dq];
                    acc[4*dq]   += p * v4.x;
                    acc[4*dq+1] += p * v4.y;
                    acc[4*dq+2] += p * v4.z;
                    acc[4*dq+3] += p * v4.w;
                }
            }
        }
        __syncthreads();
    }

    float inv = 1.0f / lsum;
    float* op = O + (size_t)tQ * DD + h * DKH;
    #pragma unroll
    for (int d = 0; d < 64; d += 4) {
        float4 o4 = make_float4(acc[d]*inv, acc[d+1]*inv, acc[d+2]*inv, acc[d+3]*inv);
        *reinterpret_cast<float4*>(op + d) = o4;
    }
}

// ---------------------------------------------------------------------------
// Residual add + LayerNorm (in place on h)
// ---------------------------------------------------------------------------
__device__ __forceinline__ float block_sum(float v, float* red)
{
    #pragma unroll
    for (int o = 16; o > 0; o >>= 1) v += __shfl_xor_sync(0xffffffffu, v, o);
    int w = threadIdx.x >> 5;
    if ((threadIdx.x & 31) == 0) red[w] = v;
    __syncthreads();
    if (threadIdx.x < 32) {
        float t = (threadIdx.x < 8) ? red[threadIdx.x] : 0.0f;
        #pragma unroll
        for (int o = 4; o > 0; o >>= 1) t += __shfl_xor_sync(0xffffffffu, t, o);
        if (threadIdx.x == 0) red[0] = t;
    }
    __syncthreads();
    float r = red[0];
    __syncthreads();
    return r;
}

__global__ __launch_bounds__(256) void add_ln_kernel(float* __restrict__ h,
                                                     const float* __restrict__ r,
                                                     const float* __restrict__ g,
                                                     const float* __restrict__ bta)
{
    __shared__ float red[32];
    const int t = blockIdx.x;
    const int tid = threadIdx.x;
    float v[4];
    float sum = 0.0f;
    #pragma unroll
    for (int i = 0; i < 4; i++) {
        int d = tid + i * 256;
        float val = h[(size_t)t * DD + d] + r[(size_t)t * DD + d];
        v[i] = val;
        sum += val;
    }
    float tot = block_sum(sum, red);
    float mu = tot * (1.0f / (float)DD);
    float sq = 0.0f;
    #pragma unroll
    for (int i = 0; i < 4; i++) { float dvi = v[i] - mu; sq += dvi * dvi; }
    float var = block_sum(sq, red) * (1.0f / (float)DD);
    float rs = rsqrtf(var + 1e-5f);
    #pragma unroll
    for (int i = 0; i < 4; i++) {
        int d = tid + i * 256;
        h[(size_t)t * DD + d] = (v[i] - mu) * rs * g[d] + bta[d];
    }
}

// ---------------------------------------------------------------------------
// Launch
// ---------------------------------------------------------------------------
extern "C" void kernel_launch(void* const* d_in, const int* in_sizes, int n_in,
                              void* d_out, int out_size)
{
    const int*   x    = (const int*)  d_in[0];
    const float* emb  = (const float*)d_in[1];
    const float* Wq   = (const float*)d_in[2];
    const float* Wk   = (const float*)d_in[3];
    const float* Wv   = (const float*)d_in[4];
    const float* Wo   = (const float*)d_in[5];
    const float* bo   = (const float*)d_in[6];
    const float* ln1g = (const float*)d_in[7];
    const float* ln1b = (const float*)d_in[8];
    const float* ln2g = (const float*)d_in[9];
    const float* ln2b = (const float*)d_in[10];
    const float* W1   = (const float*)d_in[11];
    const float* b1   = (const float*)d_in[12];
    const float* W2   = (const float*)d_in[13];
    const float* b2   = (const float*)d_in[14];
    const float* Wout = (const float*)d_in[15];
    const float* bout = (const float*)d_in[16];
    float* out = (float*)d_out;

    void* p;
    cudaGetSymbolAddress(&p, g_h);   float* h   = (float*)p;
    cudaGetSymbolAddress(&p, g_qkv); float* qkv = (float*)p;
    cudaGetSymbolAddress(&p, g_ctx); float* ctx = (float*)p;
    cudaGetSymbolAddress(&p, g_tmp); float* tmp = (float*)p;
    cudaGetSymbolAddress(&p, g_ff);  float* ff  = (float*)p;
    cudaGetSymbolAddress(&p, g_ahi); __nv_bfloat16* ahi = (__nv_bfloat16*)p;
    cudaGetSymbolAddress(&p, g_alo); __nv_bfloat16* alo = (__nv_bfloat16*)p;
    cudaGetSymbolAddress(&p, g_whi); __nv_bfloat16* whi = (__nv_bfloat16*)p;
    cudaGetSymbolAddress(&p, g_wlo); __nv_bfloat16* wlo = (__nv_bfloat16*)p;

    cudaFuncSetAttribute(gemm_mma<0>, cudaFuncAttributeMaxDynamicSharedMemorySize, GEMM_SMEM);
    cudaFuncSetAttribute(gemm_mma<1>, cudaFuncAttributeMaxDynamicSharedMemorySize, GEMM_SMEM);

    embed_kernel<<<NT, 256>>>(x, emb, h);

    const dim3 tb(32, 8);
    const int CVT_BLK = 2048;

    for (int l = 0; l < LL; l++) {
        const float* wq = Wq + (size_t)l * DD * DD;
        const float* wk = Wk + (size_t)l * DD * DD;
        const float* wv = Wv + (size_t)l * DD * DD;
        const float* wo = Wo + (size_t)l * DD * DD;
        const float* w1 = W1 + (size_t)l * DD * FF;
        const float* w2 = W2 + (size_t)l * FF * DD;

        // --- QKV fused GEMM ---
        cvt_act_kernel<<<CVT_BLK, 256>>>(h, ahi, alo, NT * DD);
        transp_cvt_kernel<<<dim3(DD/32, DD/32), tb>>>(wq, whi,                   wlo,                   DD, DD);
        transp_cvt_kernel<<<dim3(DD/32, DD/32), tb>>>(wk, whi + (size_t)DD*DD,   wlo + (size_t)DD*DD,   DD, DD);
        transp_cvt_kernel<<<dim3(DD/32, DD/32), tb>>>(wv, whi + (size_t)2*DD*DD, wlo + (size_t)2*DD*DD, DD, DD);
        gemm_mma<0><<<dim3(QKVW/BN, NT/BM), 256, GEMM_SMEM>>>(ahi, alo, whi, wlo, nullptr, qkv, NT, QKVW, DD);

        attn_kernel<<<dim3(BB * HH, SS / 64), 64>>>(qkv, x, ctx);

        // --- attention output projection ---
        cvt_act_kernel<<<CVT_BLK, 256>>>(ctx, ahi, alo, NT * DD);
        transp_cvt_kernel<<<dim3(DD/32, DD/32), tb>>>(wo, whi, wlo, DD, DD);
        gemm_mma<0><<<dim3(DD/BN, NT/BM), 256, GEMM_SMEM>>>(ahi, alo, whi, wlo, bo + l * DD, tmp, NT, DD, DD);
        add_ln_kernel<<<NT, 256>>>(h, tmp, ln1g + l * DD, ln1b + l * DD);

        // --- FFN ---
        cvt_act_kernel<<<CVT_BLK, 256>>>(h, ahi, alo, NT * DD);
        transp_cvt_kernel<<<dim3(FF/32, DD/32), tb>>>(w1, whi, wlo, DD, FF);
        gemm_mma<1><<<dim3(FF/BN, NT/BM), 256, GEMM_SMEM>>>(ahi, alo, whi, wlo, b1 + l * FF, ff, NT, FF, DD);

        cvt_act_kernel<<<CVT_BLK, 256>>>(ff, ahi, alo, NT * FF);
        transp_cvt_kernel<<<dim3(DD/32, FF/32), tb>>>(w2, whi, wlo, FF, DD);
        gemm_mma<0><<<dim3(DD/BN, NT/BM), 256, GEMM_SMEM>>>(ahi, alo, whi, wlo, b2 + l * DD, tmp, NT, DD, FF);
        add_ln_kernel<<<NT, 256>>>(h, tmp, ln2g + l * DD, ln2b + l * DD);
    }

    // --- Final output projection ---
    cvt_act_kernel<<<CVT_BLK, 256>>>(h, ahi, alo, NT * DD);
    transp_cvt_kernel<<<dim3(VV/32, DD/32), tb>>>(Wout, whi, wlo, DD, VV);
    gemm_mma<0><<<dim3(VV/BN, NT/BM), 256, GEMM_SMEM>>>(ahi, alo, whi, wlo, bout, out, NT, VV, DD);
}

// round 4
// speedup vs baseline: 2.1299x; 1.0256x over previous
#include <cuda_runtime.h>
#include <cuda_bf16.h>
#include <cstdint>
#include <cmath>

// Problem constants
#define BB   4
#define SS   1024
#define DD   1024
#define HH   16
#define DKH  64
#define LL   4
#define FF   4096
#define VV   32000
#define NT   (BB*SS)   // 4096 tokens
#define QKVW 3072      // packed q|k|v width

// GEMM tile config (mma.sync path)
#define BM 128
#define BN 128
#define BK 64                      // bf16 elems per k-stage
#define AROWB 144                  // A smem row: 128B data + 16B pad
#define AMATB (128*AROWB)          // one 128xBK bf16 matrix: 18432 B
#define ASTAGE (2*AMATB)           // Ahi|Alo per stage: 36864 B
#define BROWB 272                  // B smem row: 256B data + 16B pad
#define BHALF (64*BROWB)           // one 64x128 bf16 matrix: 17408 B
#define BBASE (2*ASTAGE)           // 73728
#define GEMM_SMEM (BBASE + 2*BHALF)   // 108544 B

// ---------------------------------------------------------------------------
// Scratch (device globals — no runtime allocation allowed)
// ---------------------------------------------------------------------------
__device__ float g_h  [NT*(size_t)DD];
__device__ float g_qkv[NT*(size_t)QKVW];
__device__ float g_tmp[NT*(size_t)DD];
__device__ __nv_bfloat16 g_ahi[NT*(size_t)DD];
__device__ __nv_bfloat16 g_alo[NT*(size_t)DD];
__device__ __nv_bfloat16 g_fhi[NT*(size_t)FF];
__device__ __nv_bfloat16 g_flo[NT*(size_t)FF];

// ---------------------------------------------------------------------------
// PTX helpers (arch-agnostic: sm_80-era instructions only)
// ---------------------------------------------------------------------------
__device__ __forceinline__ uint32_t smem_u32(const void* p) {
    uint32_t a;
    asm("{ .reg .u64 t; cvta.to.shared.u64 t, %1; cvt.u32.u64 %0, t; }" : "=r"(a) : "l"(p));
    return a;
}
__device__ __forceinline__ void cp_async16(uint32_t dst, const void* src) {
    asm volatile("cp.async.cg.shared.global [%0], [%1], 16;" :: "r"(dst), "l"(src));
}
__device__ __forceinline__ void cp_commit() {
    asm volatile("cp.async.commit_group;");
}
__device__ __forceinline__ void cp_wait1() {
    asm volatile("cp.async.wait_group 1;");
}
__device__ __forceinline__ void cp_wait0() {
    asm volatile("cp.async.wait_group 0;");
}
__device__ __forceinline__ void ldmx4(uint32_t addr, uint32_t& r0, uint32_t& r1,
                                      uint32_t& r2, uint32_t& r3) {
    asm volatile("ldmatrix.sync.aligned.m8n8.x4.shared.b16 {%0,%1,%2,%3}, [%4];"
                 : "=r"(r0), "=r"(r1), "=r"(r2), "=r"(r3) : "r"(addr));
}
__device__ __forceinline__ void ldmx4t(uint32_t addr, uint32_t& r0, uint32_t& r1,
                                       uint32_t& r2, uint32_t& r3) {
    asm volatile("ldmatrix.sync.aligned.m8n8.x4.trans.shared.b16 {%0,%1,%2,%3}, [%4];"
                 : "=r"(r0), "=r"(r1), "=r"(r2), "=r"(r3) : "r"(addr));
}
__device__ __forceinline__ void mma_bf16(float* c, const uint32_t* a, const uint32_t* b) {
    asm volatile("mma.sync.aligned.m16n8k16.row.col.f32.bf16.bf16.f32 "
                 "{%0,%1,%2,%3}, {%4,%5,%6,%7}, {%8,%9}, {%0,%1,%2,%3};"
                 : "+f"(c[0]), "+f"(c[1]), "+f"(c[2]), "+f"(c[3])
                 : "r"(a[0]), "r"(a[1]), "r"(a[2]), "r"(a[3]), "r"(b[0]), "r"(b[1]));
}
__device__ __forceinline__ uint32_t bf2_bits(__nv_bfloat162 v) {
    return *reinterpret_cast<uint32_t*>(&v);
}
// split a float pair into hi/lo bf16x2 words
__device__ __forceinline__ void split2(float a, float b, uint32_t& hw, uint32_t& lw) {
    __nv_bfloat162 h = __floats2bfloat162_rn(a, b);
    float la = a - __low2float(h);
    float lb = b - __high2float(h);
    __nv_bfloat162 l = __floats2bfloat162_rn(la, lb);
    hw = bf2_bits(h);
    lw = bf2_bits(l);
}

// ---------------------------------------------------------------------------
// Embedding + positional encoding; writes fp32 h AND bf16 hi/lo split
// ---------------------------------------------------------------------------
__global__ __launch_bounds__(256) void embed_kernel(const int* __restrict__ x,
                                                    const float* __restrict__ emb,
                                                    float* __restrict__ h,
                                                    __nv_bfloat16* __restrict__ ahi,
                                                    __nv_bfloat16* __restrict__ alo)
{
    int t = blockIdx.x;
    int s = t & (SS - 1);
    int tok = x[t];
    const float* e = emb + (size_t)tok * DD;
    const float negln = -9.210340371976184f;
    size_t base = (size_t)t * DD;
    for (int d0 = threadIdx.x * 2; d0 < DD; d0 += blockDim.x * 2) {
        float v[2];
        #pragma unroll
        for (int j = 0; j < 2; j++) {
            int d = d0 + j;
            int i2 = (d >> 1) * 2;
            float div = expf((float)i2 * (negln / (float)DD));
            float ang = (float)s * div;
            float pe = (d & 1) ? cosf(ang) : sinf(ang);
            v[j] = e[d] * 32.0f + pe;
        }
        h[base + d0] = v[0];
        h[base + d0 + 1] = v[1];
        uint32_t hw, lw;
        split2(v[0], v[1], hw, lw);
        *reinterpret_cast<uint32_t*>(ahi + base + d0) = hw;
        *reinterpret_cast<uint32_t*>(alo + base + d0) = lw;
    }
}

// ---------------------------------------------------------------------------
// bf16x3 GEMM via mma.sync: C[M,N] = A[M,K] @ W[K,N] (+bias)(+GELU)
// A: pre-split hi/lo bf16 [M,K]. W: ORIGINAL fp32 [K,N], split on the fly.
// BM=BN=128, BK=64, 256 threads (8 warps, 64x32 warp tiles).
// A double-buffered via cp.async; W staged through registers (LDG->cvt->STS),
// B fragments via ldmatrix.trans. Output fp32 (OUTBF=0) or bf16 hi/lo (OUTBF=1).
// ---------------------------------------------------------------------------
__device__ __forceinline__ void stage_loadA(uint32_t sdst,
                                            const __nv_bfloat16* Ahi, const __nv_bfloat16* Alo,
                                            int rowBase, int K, int k0, int tid)
{
    #pragma unroll
    for (int i = 0; i < 4; i++) {
        int idx = tid + i * 256;           // 0..1023
        int r  = idx >> 3;
        int ch = idx & 7;
        uint32_t so = (uint32_t)r * AROWB + (uint32_t)ch * 16;
        size_t gA = (size_t)(rowBase + r) * K + k0 + ch * 8;
        cp_async16(sdst + so,         Ahi + gA);
        cp_async16(sdst + AMATB + so, Alo + gA);
    }
}

__device__ __forceinline__ void loadB_regs(float4* breg, const float* __restrict__ W,
                                           int Nw, int colBase, int k0, int tid)
{
    int r  = tid >> 2;
    int cq = tid & 3;
    const float* base = W + (size_t)(k0 + r) * Nw + colBase + cq * 4;
    #pragma unroll
    for (int i = 0; i < 8; i++)
        breg[i] = *reinterpret_cast<const float4*>(base + i * 16);
}

__device__ __forceinline__ void stsB(uint32_t bB, const float4* breg, int tid)
{
    int r  = tid >> 2;
    int cq = tid & 3;
    uint32_t base = bB + (uint32_t)r * BROWB + (uint32_t)cq * 8;
    #pragma unroll
    for (int i = 0; i < 8; i++) {
        float4 f = breg[i];
        uint2 uh, ul;
        split2(f.x, f.y, uh.x, ul.x);
        split2(f.z, f.w, uh.y, ul.y);
        uint32_t a = base + (uint32_t)i * 32;
        asm volatile("st.shared.v2.b32 [%0], {%1, %2};" :: "r"(a), "r"(uh.x), "r"(uh.y));
        asm volatile("st.shared.v2.b32 [%0], {%1, %2};" :: "r"(a + BHALF), "r"(ul.x), "r"(ul.y));
    }
}

template<int ACT, int OUTBF>
__global__ __launch_bounds__(256) void gemm_mma(const __nv_bfloat16* __restrict__ Ahi,
                                                const __nv_bfloat16* __restrict__ Alo,
                                                const float* __restrict__ W,
                                                const float* __restrict__ bias,
                                                float* __restrict__ C,
                                                __nv_bfloat16* __restrict__ Chi,
                                                __nv_bfloat16* __restrict__ Clo,
                                                int M, int Nw, int K, int ldC)
{
    extern __shared__ char smem[];
    const uint32_t sb = smem_u32(smem);
    const int tid  = threadIdx.x;
    const int wid  = tid >> 5;
    const int lane = tid & 31;
    const int rowBase = blockIdx.x * BM;
    const int colBase = blockIdx.y * BN;
    const int m0 = (wid >> 2) * 64;     // warp M offset
    const int n0 = (wid & 3) * 32;      // warp N offset
    const int g  = lane >> 3;
    const int lr = lane & 7;

    float acc[4][4][4];
    #pragma unroll
    for (int mt = 0; mt < 4; mt++)
        #pragma unroll
        for (int nt = 0; nt < 4; nt++)
            #pragma unroll
            for (int e = 0; e < 4; e++) acc[mt][nt][e] = 0.0f;

    const int KT = K / BK;
    const uint32_t bB = sb + BBASE;

    float4 breg[8];
    loadB_regs(breg, W, Nw, colBase, 0, tid);
    stage_loadA(sb, Ahi, Alo, rowBase, K, 0, tid);
    cp_commit();

    for (int it = 0; it < KT; it++) {
        const int buf = it & 1;
        if (it + 1 < KT) {
            stage_loadA(sb + (buf ^ 1) * ASTAGE, Ahi, Alo, rowBase, K, (it + 1) * BK, tid);
            cp_commit();
            cp_wait1();
        } else {
            cp_wait0();
        }
        stsB(bB, breg, tid);
        __syncthreads();
        if (it + 1 < KT) loadB_regs(breg, W, Nw, colBase, (it + 1) * BK, tid);

        const uint32_t aB = sb + buf * ASTAGE;
        #pragma unroll
        for (int ks = 0; ks < 4; ks++) {
            uint32_t Ah[4][4], Al[4][4];
            #pragma unroll
            for (int mt = 0; mt < 4; mt++) {
                int r  = m0 + mt * 16 + (g & 1) * 8 + lr;
                int ch = ks * 2 + (g >> 1);
                uint32_t ad = aB + (uint32_t)r * AROWB + (uint32_t)ch * 16;
                ldmx4(ad,         Ah[mt][0], Ah[mt][1], Ah[mt][2], Ah[mt][3]);
                ldmx4(ad + AMATB, Al[mt][0], Al[mt][1], Al[mt][2], Al[mt][3]);
            }
            uint32_t Bh[4][2], Bl[4][2];
            #pragma unroll
            for (int p = 0; p < 2; p++) {
                int kr = ks * 16 + (lane & 15);
                int nc = n0 + p * 16 + (lane >> 4) * 8;
                uint32_t bd = bB + (uint32_t)kr * BROWB + (uint32_t)nc * 2;
                ldmx4t(bd,         Bh[2*p][0], Bh[2*p][1], Bh[2*p+1][0], Bh[2*p+1][1]);
                ldmx4t(bd + BHALF, Bl[2*p][0], Bl[2*p][1], Bl[2*p+1][0], Bl[2*p+1][1]);
            }
            #pragma unroll
            for (int mt = 0; mt < 4; mt++)
                #pragma unroll
                for (int nt = 0; nt < 4; nt++) {
                    mma_bf16(acc[mt][nt], Ah[mt], Bh[nt]);
                    mma_bf16(acc[mt][nt], Ah[mt], Bl[nt]);
                    mma_bf16(acc[mt][nt], Al[mt], Bh[nt]);
                }
        }
        __syncthreads();
    }

    // Epilogue
    const int crow = lane >> 2;
    const int ccol = (lane & 3) * 2;
    #pragma unroll
    for (int mt = 0; mt < 4; mt++) {
        #pragma unroll
        for (int nt = 0; nt < 4; nt++) {
            int col = colBase + n0 + nt * 8 + ccol;
            float b0 = 0.0f, b1 = 0.0f;
            if (bias) { b0 = __ldg(bias + col); b1 = __ldg(bias + col + 1); }
            #pragma unroll
            for (int half = 0; half < 2; half++) {
                int row = rowBase + m0 + mt * 16 + crow + half * 8;
                float v0 = acc[mt][nt][half * 2 + 0] + b0;
                float v1 = acc[mt][nt][half * 2 + 1] + b1;
                if (ACT == 1) {
                    v0 = 0.5f * v0 * (1.0f + erff(v0 * 0.7071067811865476f));
                    v1 = 0.5f * v1 * (1.0f + erff(v1 * 0.7071067811865476f));
                }
                if (OUTBF) {
                    uint32_t hw, lw;
                    split2(v0, v1, hw, lw);
                    *reinterpret_cast<uint32_t*>(Chi + (size_t)row * ldC + col) = hw;
                    *reinterpret_cast<uint32_t*>(Clo + (size_t)row * ldC + col) = lw;
                } else {
                    *reinterpret_cast<float2*>(&C[(size_t)row * ldC + col]) = make_float2(v0, v1);
                }
            }
        }
    }
}

// ---------------------------------------------------------------------------
// Flash attention (fp32) on packed qkv [NT, 3072]; emits bf16 hi/lo ctx split.
// ---------------------------------------------------------------------------
__global__ __launch_bounds__(64) void attn_kernel(const float* __restrict__ QKV,
                                                  const int* __restrict__ x,
                                                  __nv_bfloat16* __restrict__ Ohi,
                                                  __nv_bfloat16* __restrict__ Olo)
{
    __shared__ float Ks[32][64];
    __shared__ float Vs[32][64];
    __shared__ int   validS[32];

    const int bh = blockIdx.x;
    const int b  = bh >> 4;
    const int h  = bh & 15;
    const int qt = blockIdx.y;
    const int tid = threadIdx.x;
    const int qrow = qt * 64 + tid;
    const int tQ = b * SS + qrow;

    const float* qp = QKV + (size_t)tQ * QKVW + h * DKH;
    float qreg[64], acc[64];
    #pragma unroll
    for (int d = 0; d < 64; d += 4) {
        float4 f = *reinterpret_cast<const float4*>(qp + d);
        qreg[d] = f.x; qreg[d+1] = f.y; qreg[d+2] = f.z; qreg[d+3] = f.w;
    }
    #pragma unroll
    for (int d = 0; d < 64; d++) acc[d] = 0.0f;

    float mrun = -1e30f, lsum = 0.0f;
    const int ntiles = 2 * qt + 2;

    for (int kt = 0; kt < ntiles; kt++) {
        const int kbase = kt * 32;
        #pragma unroll 4
        for (int i = 0; i < 32; i++) {
            size_t off = (size_t)(b * SS + kbase + i) * QKVW + h * DKH + tid;
            Ks[i][tid] = QKV[off + 1024];
            Vs[i][tid] = QKV[off + 2048];
        }
        if (tid < 32) validS[tid] = (x[b * SS + kbase + tid] != 0);
        __syncthreads();

        int jmax = qrow - kbase + 1;
        if (jmax > 32) jmax = 32;
        if (jmax > 0) {
            float s[32];
            float tmax = -1e30f;
            #pragma unroll
            for (int j = 0; j < 32; j++) {
                if (j < jmax) {
                    float sum = 0.0f;
                    const float4* kr = reinterpret_cast<const float4*>(Ks[j]);
                    #pragma unroll
                    for (int dq = 0; dq < 16; dq++) {
                        float4 k4 = kr[dq];
                        sum += qreg[4*dq]   * k4.x;
                        sum += qreg[4*dq+1] * k4.y;
                        sum += qreg[4*dq+2] * k4.z;
                        sum += qreg[4*dq+3] * k4.w;
                    }
                    sum *= 0.125f;
                    if (!validS[j]) sum = -1e30f;
                    s[j] = sum;
                    tmax = fmaxf(tmax, sum);
                } else {
                    s[j] = -1e30f;
                }
            }
            float mnew = fmaxf(mrun, tmax);
            float corr = __expf(mrun - mnew);
            lsum *= corr;
            #pragma unroll
            for (int d = 0; d < 64; d++) acc[d] *= corr;
            mrun = mnew;
            #pragma unroll
            for (int j = 0; j < 32; j++) {
                float p = __expf(s[j] - mrun);
                lsum += p;
                const float4* vr = reinterpret_cast<const float4*>(Vs[j]);
                #pragma unroll
                for (int dq = 0; dq < 16; dq++) {
                    float4 v4 = vr[dq];
                    acc[4*dq]   += p * v4.x;
                    acc[4*dq+1] += p * v4.y;
                    acc[4*dq+2] += p * v4.z;
                    acc[4*dq+3] += p * v4.w;
                }
            }
        }
        __syncthreads();
    }

    float inv = 1.0f / lsum;
    size_t ob = (size_t)tQ * DD + h * DKH;
    #pragma unroll
    for (int d = 0; d < 64; d += 2) {
        uint32_t hw, lw;
        split2(acc[d] * inv, acc[d+1] * inv, hw, lw);
        *reinterpret_cast<uint32_t*>(Ohi + ob + d) = hw;
        *reinterpret_cast<uint32_t*>(Olo + ob + d) = lw;
    }
}

// ---------------------------------------------------------------------------
// Residual add + LayerNorm (in place on h); also emits bf16 hi/lo split
// ---------------------------------------------------------------------------
__device__ __forceinline__ float block_sum(float v, float* red)
{
    #pragma unroll
    for (int o = 16; o > 0; o >>= 1) v += __shfl_xor_sync(0xffffffffu, v, o);
    int w = threadIdx.x >> 5;
    if ((threadIdx.x & 31) == 0) red[w] = v;
    __syncthreads();
    if (threadIdx.x < 32) {
        float t = (threadIdx.x < 8) ? red[threadIdx.x] : 0.0f;
        #pragma unroll
        for (int o = 4; o > 0; o >>= 1) t += __shfl_xor_sync(0xffffffffu, t, o);
        if (threadIdx.x == 0) red[0] = t;
    }
    __syncthreads();
    float r = red[0];
    __syncthreads();
    return r;
}

__global__ __launch_bounds__(256) void add_ln_kernel(float* __restrict__ h,
                                                     const float* __restrict__ r,
                                                     const float* __restrict__ g,
                                                     const float* __restrict__ bta,
                                                     __nv_bfloat16* __restrict__ ahi,
                                                     __nv_bfloat16* __restrict__ alo)
{
    __shared__ float red[32];
    const int t = blockIdx.x;
    const int tid = threadIdx.x;
    size_t base = (size_t)t * DD;
    float v[4];
    float sum = 0.0f;
    #pragma unroll
    for (int i = 0; i < 4; i++) {
        int d = tid * 2 + (i & 1) + (i >> 1) * 512;
        float val = h[base + d] + r[base + d];
        v[i] = val;
        sum += val;
    }
    float tot = block_sum(sum, red);
    float mu = tot * (1.0f / (float)DD);
    float sq = 0.0f;
    #pragma unroll
    for (int i = 0; i < 4; i++) { float dvi = v[i] - mu; sq += dvi * dvi; }
    float var = block_sum(sq, red) * (1.0f / (float)DD);
    float rs = rsqrtf(var + 1e-5f);
    #pragma unroll
    for (int p = 0; p < 2; p++) {
        int d = tid * 2 + p * 512;
        float o0 = (v[p*2]   - mu) * rs * g[d]     + bta[d];
        float o1 = (v[p*2+1] - mu) * rs * g[d + 1] + bta[d + 1];
        h[base + d]     = o0;
        h[base + d + 1] = o1;
        uint32_t hw, lw;
        split2(o0, o1, hw, lw);
        *reinterpret_cast<uint32_t*>(ahi + base + d) = hw;
        *reinterpret_cast<uint32_t*>(alo + base + d) = lw;
    }
}

// ---------------------------------------------------------------------------
// Launch
// ---------------------------------------------------------------------------
extern "C" void kernel_launch(void* const* d_in, const int* in_sizes, int n_in,
                              void* d_out, int out_size)
{
    const int*   x    = (const int*)  d_in[0];
    const float* emb  = (const float*)d_in[1];
    const float* Wq   = (const float*)d_in[2];
    const float* Wk   = (const float*)d_in[3];
    const float* Wv   = (const float*)d_in[4];
    const float* Wo   = (const float*)d_in[5];
    const float* bo   = (const float*)d_in[6];
    const float* ln1g = (const float*)d_in[7];
    const float* ln1b = (const float*)d_in[8];
    const float* ln2g = (const float*)d_in[9];
    const float* ln2b = (const float*)d_in[10];
    const float* W1   = (const float*)d_in[11];
    const float* b1   = (const float*)d_in[12];
    const float* W2   = (const float*)d_in[13];
    const float* b2   = (const float*)d_in[14];
    const float* Wout = (const float*)d_in[15];
    const float* bout = (const float*)d_in[16];
    float* out = (float*)d_out;

    void* p;
    cudaGetSymbolAddress(&p, g_h);   float* h   = (float*)p;
    cudaGetSymbolAddress(&p, g_qkv); float* qkv = (float*)p;
    cudaGetSymbolAddress(&p, g_tmp); float* tmp = (float*)p;
    cudaGetSymbolAddress(&p, g_ahi); __nv_bfloat16* ahi = (__nv_bfloat16*)p;
    cudaGetSymbolAddress(&p, g_alo); __nv_bfloat16* alo = (__nv_bfloat16*)p;
    cudaGetSymbolAddress(&p, g_fhi); __nv_bfloat16* fhi = (__nv_bfloat16*)p;
    cudaGetSymbolAddress(&p, g_flo); __nv_bfloat16* flo = (__nv_bfloat16*)p;

    cudaFuncSetAttribute(gemm_mma<0,0>, cudaFuncAttributeMaxDynamicSharedMemorySize, GEMM_SMEM);
    cudaFuncSetAttribute(gemm_mma<1,1>, cudaFuncAttributeMaxDynamicSharedMemorySize, GEMM_SMEM);

    embed_kernel<<<NT, 256>>>(x, emb, h, ahi, alo);

    const dim3 gD(NT/BM, DD/BN);     // 32 x 8
    const dim3 gF(NT/BM, FF/BN);     // 32 x 32
    const dim3 gV(NT/BM, VV/BN);     // 32 x 250

    for (int l = 0; l < LL; l++) {
        const float* wq = Wq + (size_t)l * DD * DD;
        const float* wk = Wk + (size_t)l * DD * DD;
        const float* wv = Wv + (size_t)l * DD * DD;
        const float* wo = Wo + (size_t)l * DD * DD;
        const float* w1 = W1 + (size_t)l * DD * FF;
        const float* w2 = W2 + (size_t)l * FF * DD;

        // QKV projections (C strided into packed qkv buffer)
        gemm_mma<0,0><<<gD, 256, GEMM_SMEM>>>(ahi, alo, wq, nullptr, qkv,        nullptr, nullptr, NT, DD, DD, QKVW);
        gemm_mma<0,0><<<gD, 256, GEMM_SMEM>>>(ahi, alo, wk, nullptr, qkv + 1024, nullptr, nullptr, NT, DD, DD, QKVW);
        gemm_mma<0,0><<<gD, 256, GEMM_SMEM>>>(ahi, alo, wv, nullptr, qkv + 2048, nullptr, nullptr, NT, DD, DD, QKVW);

        attn_kernel<<<dim3(BB * HH, SS / 64), 64>>>(qkv, x, ahi, alo);   // ctx split

        gemm_mma<0,0><<<gD, 256, GEMM_SMEM>>>(ahi, alo, wo, bo + l * DD, tmp, nullptr, nullptr, NT, DD, DD, DD);
        add_ln_kernel<<<NT, 256>>>(h, tmp, ln1g + l * DD, ln1b + l * DD, ahi, alo);

        gemm_mma<1,1><<<gF, 256, GEMM_SMEM>>>(ahi, alo, w1, b1 + l * FF, nullptr, fhi, flo, NT, FF, DD, FF);
        gemm_mma<0,0><<<gD, 256, GEMM_SMEM>>>(fhi, flo, w2, b2 + l * DD, tmp, nullptr, nullptr, NT, DD, FF, DD);
        add_ln_kernel<<<NT, 256>>>(h, tmp, ln2g + l * DD, ln2b + l * DD, ahi, alo);
    }

    gemm_mma<0,0><<<gV, 256, GEMM_SMEM>>>(ahi, alo, Wout, bout, out, nullptr, nullptr, NT, VV, DD, VV);
}